// round 5
// baseline (speedup 1.0000x reference)
#include <cuda_runtime.h>
#include <cuda_bf16.h>
#include <cstdint>

// ---------------- problem constants ----------------
#define BATCH 1024
#define NN    128
#define DIN   256
#define HID   256
#define DOUT  256
#define KD    512
#define MROWS (BATCH*NN)
#define GK    256

#define OUT_ELEMS ((long)MROWS*DOUT)
#define ATT_ELEMS ((long)BATCH*NN*NN)
#define TOT_ELEMS (OUT_ELEMS + ATT_ELEMS)

// ---------------- scratch ----------------
__device__ __align__(16) float g_att_dummy[ATT_ELEMS];

__device__ __align__(16) __nv_bfloat16 g_xhi[(long)MROWS*GK];
__device__ __align__(16) __nv_bfloat16 g_xlo[(long)MROWS*GK];
__device__ __align__(16) __nv_bfloat16 g_qhi[(long)MROWS*KD];
__device__ __align__(16) __nv_bfloat16 g_qlo[(long)MROWS*KD];
__device__ __align__(16) __nv_bfloat16 g_khi[(long)MROWS*KD];
__device__ __align__(16) __nv_bfloat16 g_klo[(long)MROWS*KD];
__device__ __align__(16) __nv_bfloat16 g_vhi[(long)MROWS*HID];
__device__ __align__(16) __nv_bfloat16 g_vlo[(long)MROWS*HID];
__device__ __align__(16) __nv_bfloat16 g_chi[(long)MROWS*HID];
__device__ __align__(16) __nv_bfloat16 g_clo[(long)MROWS*HID];

__device__ __align__(16) __nv_bfloat16 g_wvhi[GK*HID], g_wvlo[GK*HID];
__device__ __align__(16) __nv_bfloat16 g_wqhi[GK*KD],  g_wqlo[GK*KD];
__device__ __align__(16) __nv_bfloat16 g_wkhi[GK*KD],  g_wklo[GK*KD];
__device__ __align__(16) __nv_bfloat16 g_wohi[HID*DOUT], g_wolo[HID*DOUT];

// ---------------- helpers ----------------
__device__ __forceinline__ uint32_t smem_u32(const void* p) {
    uint32_t a;
    asm("{ .reg .u64 t; cvta.to.shared.u64 t, %1; cvt.u32.u64 %0, t; }" : "=r"(a) : "l"(p));
    return a;
}
__device__ __forceinline__ void split_bf16(float a, __nv_bfloat16& h, __nv_bfloat16& l) {
    h = __float2bfloat16_rn(a);
    l = __float2bfloat16_rn(a - __bfloat162float(h));
}

#define LDSM4(r0, r1, r2, r3, addr) \
    asm volatile("ldmatrix.sync.aligned.m8n8.x4.shared.b16 {%0,%1,%2,%3}, [%4];" \
                 : "=r"(r0), "=r"(r1), "=r"(r2), "=r"(r3) : "r"(addr))

#define MMA16816(d, a0, a1, a2, a3, b0, b1) \
    asm volatile("mma.sync.aligned.m16n8k16.row.col.f32.bf16.bf16.f32 " \
                 "{%0,%1,%2,%3},{%4,%5,%6,%7},{%8,%9},{%0,%1,%2,%3};" \
                 : "+f"((d)[0]), "+f"((d)[1]), "+f"((d)[2]), "+f"((d)[3]) \
                 : "r"(a0), "r"(a1), "r"(a2), "r"(a3), "r"(b0), "r"(b1))

#define CP16(saddr, gptr) \
    asm volatile("cp.async.cg.shared.global [%0], [%1], 16;" :: "r"(saddr), "l"(gptr))
#define CP_COMMIT() asm volatile("cp.async.commit_group;" ::: "memory")
#define CP_WAIT1()  asm volatile("cp.async.wait_group 1;" ::: "memory")
#define CP_WAIT0()  asm volatile("cp.async.wait_group 0;" ::: "memory")

// ---------------- prep kernels ----------------
__global__ void split_x_kernel(const float4* __restrict__ x,
                               uint2* __restrict__ hi, uint2* __restrict__ lo, long n4) {
    long i = (long)blockIdx.x * blockDim.x + threadIdx.x;
    if (i >= n4) return;
    float4 a = x[i];
    __nv_bfloat16 h0, l0, h1, l1, h2, l2, h3, l3;
    split_bf16(a.x, h0, l0); split_bf16(a.y, h1, l1);
    split_bf16(a.z, h2, l2); split_bf16(a.w, h3, l3);
    __nv_bfloat162 hA = __halves2bfloat162(h0, h1), hB = __halves2bfloat162(h2, h3);
    __nv_bfloat162 lA = __halves2bfloat162(l0, l1), lB = __halves2bfloat162(l2, l3);
    hi[i] = make_uint2(*(uint32_t*)&hA, *(uint32_t*)&hB);
    lo[i] = make_uint2(*(uint32_t*)&lA, *(uint32_t*)&lB);
}

__global__ void prep_weight(const float* __restrict__ W, __nv_bfloat16* __restrict__ hi,
                            __nv_bfloat16* __restrict__ lo, int K, int N) {
    int idx = blockIdx.x * 256 + threadIdx.x;
    if (idx >= K * N) return;
    int k = idx / N, n = idx % N;
    __nv_bfloat16 h, l;
    split_bf16(W[idx], h, l);
    hi[(long)n * K + k] = h;
    lo[(long)n * K + k] = l;
}

// =====================================================================
// bf16x3 mma GEMM with 2-stage cp.async pipeline.
// CTA 128x128, K=256 in 4 tiles of 64, 8 warps (4m x 2n).
// =====================================================================
#define ROWB 144
#define TILE_B (128 * ROWB)
#define SSTRIDE (4 * TILE_B)          // one stage: Ah, Al, Bh, Bl
#define GEMM_SMEM (2 * SSTRIDE)       // 147456

__global__ void __launch_bounds__(256, 1) mma_gemm(
    const __nv_bfloat16* __restrict__ Ahi, const __nv_bfloat16* __restrict__ Alo,
    const __nv_bfloat16* __restrict__ Bhi, const __nv_bfloat16* __restrict__ Blo,
    const float* __restrict__ bias, float* __restrict__ C,
    __nv_bfloat16* __restrict__ Chi, __nv_bfloat16* __restrict__ Clo,
    int Ncols, int mode)
{
    extern __shared__ char smc[];
    const uint32_t s0 = smem_u32(smc);

    const int tid  = threadIdx.x;
    const int wid  = tid >> 5;
    const int lane = tid & 31;
    const int wm   = wid >> 1;
    const int wn   = wid & 1;

    const long mBase = (long)blockIdx.y * 128;
    const int  nBase = blockIdx.x * 128;

    const __nv_bfloat16* Ah = Ahi + mBase * GK;
    const __nv_bfloat16* Al = Alo + mBase * GK;
    const __nv_bfloat16* Bh = Bhi + (long)nBase * GK;
    const __nv_bfloat16* Bl = Blo + (long)nBase * GK;

    float acc[2][8][4];
    #pragma unroll
    for (int a = 0; a < 2; a++)
        #pragma unroll
        for (int b = 0; b < 8; b++)
            #pragma unroll
            for (int c = 0; c < 4; c++) acc[a][b][c] = 0.f;

    const int lrow = tid >> 3;
    const int lq   = tid & 7;
    const uint32_t aOff = (uint32_t)(wm * 32 + (lane & 15)) * ROWB + (lane >> 4) * 16;
    const uint32_t bOff = (uint32_t)(wn * 64 + (lane & 15)) * ROWB + (lane >> 4) * 16;

    // stage loader: 16 cp.async per thread
    auto load_stage = [&](int kt, int stg) {
        const uint32_t sb = s0 + (uint32_t)stg * SSTRIDE;
        #pragma unroll
        for (int it = 0; it < 4; it++) {
            int r = lrow + it * 32;
            long gsrc = (long)r * GK + kt * 64 + lq * 8;
            uint32_t sdst = (uint32_t)r * ROWB + lq * 16;
            CP16(sb + 0 * TILE_B + sdst, Ah + gsrc);
            CP16(sb + 1 * TILE_B + sdst, Al + gsrc);
            CP16(sb + 2 * TILE_B + sdst, Bh + gsrc);
            CP16(sb + 3 * TILE_B + sdst, Bl + gsrc);
        }
        CP_COMMIT();
    };

    load_stage(0, 0);
    for (int kt = 0; kt < 4; kt++) {
        if (kt < 3) { load_stage(kt + 1, (kt + 1) & 1); CP_WAIT1(); }
        else        { CP_WAIT0(); }
        __syncthreads();

        const uint32_t sb  = s0 + (uint32_t)(kt & 1) * SSTRIDE;
        const uint32_t sAh = sb;
        const uint32_t sAl = sb + TILE_B;
        const uint32_t sBh = sb + 2 * TILE_B;
        const uint32_t sBl = sb + 3 * TILE_B;

        #pragma unroll
        for (int ks = 0; ks < 4; ks++) {
            const uint32_t kByte = ks * 32;
            uint32_t Bf[16], Af[8], Af2[8];
            #pragma unroll
            for (int c = 0; c < 4; c++) {
                uint32_t ad = sBh + bOff + (uint32_t)c * (16 * ROWB) + kByte;
                LDSM4(Bf[c*4+0], Bf[c*4+1], Bf[c*4+2], Bf[c*4+3], ad);
            }
            #pragma unroll
            for (int mt = 0; mt < 2; mt++) {
                uint32_t ad = sAh + aOff + (uint32_t)mt * (16 * ROWB) + kByte;
                LDSM4(Af[mt*4+0], Af[mt*4+1], Af[mt*4+2], Af[mt*4+3], ad);
            }
            #pragma unroll
            for (int mt = 0; mt < 2; mt++) {
                uint32_t ad = sAl + aOff + (uint32_t)mt * (16 * ROWB) + kByte;
                LDSM4(Af2[mt*4+0], Af2[mt*4+1], Af2[mt*4+2], Af2[mt*4+3], ad);
            }
            #pragma unroll
            for (int mt = 0; mt < 2; mt++)
                #pragma unroll
                for (int c = 0; c < 4; c++) {
                    MMA16816(acc[mt][c*2+0], Af[mt*4+0], Af[mt*4+1], Af[mt*4+2], Af[mt*4+3],
                             Bf[c*4+0], Bf[c*4+2]);
                    MMA16816(acc[mt][c*2+1], Af[mt*4+0], Af[mt*4+1], Af[mt*4+2], Af[mt*4+3],
                             Bf[c*4+1], Bf[c*4+3]);
                    MMA16816(acc[mt][c*2+0], Af2[mt*4+0], Af2[mt*4+1], Af2[mt*4+2], Af2[mt*4+3],
                             Bf[c*4+0], Bf[c*4+2]);
                    MMA16816(acc[mt][c*2+1], Af2[mt*4+0], Af2[mt*4+1], Af2[mt*4+2], Af2[mt*4+3],
                             Bf[c*4+1], Bf[c*4+3]);
                }
            #pragma unroll
            for (int c = 0; c < 4; c++) {
                uint32_t ad = sBl + bOff + (uint32_t)c * (16 * ROWB) + kByte;
                LDSM4(Bf[c*4+0], Bf[c*4+1], Bf[c*4+2], Bf[c*4+3], ad);
            }
            #pragma unroll
            for (int mt = 0; mt < 2; mt++)
                #pragma unroll
                for (int c = 0; c < 4; c++) {
                    MMA16816(acc[mt][c*2+0], Af[mt*4+0], Af[mt*4+1], Af[mt*4+2], Af[mt*4+3],
                             Bf[c*4+0], Bf[c*4+2]);
                    MMA16816(acc[mt][c*2+1], Af[mt*4+0], Af[mt*4+1], Af[mt*4+2], Af[mt*4+3],
                             Bf[c*4+1], Bf[c*4+3]);
                }
        }
        __syncthreads();
    }

    const int group = lane >> 2;
    const int tig   = lane & 3;
    #pragma unroll
    for (int mt = 0; mt < 2; mt++) {
        long r0 = mBase + wm * 32 + mt * 16 + group;
        long r1 = r0 + 8;
        #pragma unroll
        for (int nt = 0; nt < 8; nt++) {
            int col = nBase + wn * 64 + (nt >> 1) * 16 + (nt & 1) * 8 + tig * 2;
            float b0 = bias[col], b1 = bias[col + 1];
            float v00 = fmaxf(acc[mt][nt][0] + b0, 0.f);
            float v01 = fmaxf(acc[mt][nt][1] + b1, 0.f);
            float v10 = fmaxf(acc[mt][nt][2] + b0, 0.f);
            float v11 = fmaxf(acc[mt][nt][3] + b1, 0.f);
            if (mode == 0) {
                *(float2*)(C + r0 * Ncols + col) = make_float2(v00, v01);
                *(float2*)(C + r1 * Ncols + col) = make_float2(v10, v11);
            } else {
                __nv_bfloat16 h00, l00, h01, l01, h10, l10, h11, l11;
                split_bf16(v00, h00, l00); split_bf16(v01, h01, l01);
                split_bf16(v10, h10, l10); split_bf16(v11, h11, l11);
                *(__nv_bfloat162*)(Chi + r0 * Ncols + col) = __halves2bfloat162(h00, h01);
                *(__nv_bfloat162*)(Clo + r0 * Ncols + col) = __halves2bfloat162(l00, l01);
                *(__nv_bfloat162*)(Chi + r1 * Ncols + col) = __halves2bfloat162(h10, h11);
                *(__nv_bfloat162*)(Clo + r1 * Ncols + col) = __halves2bfloat162(l10, l11);
            }
        }
    }
}

// =====================================================================
// Fused attention, all-HMMA, phase-1 with 2-stage cp.async pipeline.
// smem (bytes):
//   [0,65536)            s_sc fp32 scores
//   [65536,212992)       phase1 pipeline: 2 stages x (qh/ql/kh/kl x 18432)
//   [65536,100352)       Phi (128 x 272)   (phase2/3, reuse)
//   [100352,135168)      Plo
//   [135168,152576)      vThi (64 x 272)
//   [152576,169984)      vTlo
// =====================================================================
#define ROWP 272
#define OFF_PIPE 65536
#define OFF_PHI 65536
#define OFF_PLO 100352
#define OFF_VTH 135168
#define OFF_VTL 152576
#define ATT_SMEM (OFF_PIPE + 2 * SSTRIDE)   // 212992

__global__ void __launch_bounds__(256, 1) attention_mma(
    const __nv_bfloat16* __restrict__ qhi, const __nv_bfloat16* __restrict__ qlo,
    const __nv_bfloat16* __restrict__ khi, const __nv_bfloat16* __restrict__ klo,
    const __nv_bfloat16* __restrict__ vhi, const __nv_bfloat16* __restrict__ vlo,
    const float* __restrict__ mask, float* __restrict__ att,
    __nv_bfloat16* __restrict__ ctxhi, __nv_bfloat16* __restrict__ ctxlo)
{
    extern __shared__ char sm[];
    float* s_sc = (float*)sm;
    const uint32_t s0 = smem_u32(sm);

    const int b    = blockIdx.x;
    const int tid  = threadIdx.x;
    const int wid  = tid >> 5;
    const int lane = tid & 31;
    const int wm   = wid >> 1;
    const int wn   = wid & 1;
    const int lrow = tid >> 3;
    const int lq   = tid & 7;
    const int group = lane >> 2;
    const int tig   = lane & 3;

    // ---------------- phase 1: S = q @ k^T ----------------
    {
        const __nv_bfloat16* qh = qhi + (long)b * NN * KD;
        const __nv_bfloat16* ql = qlo + (long)b * NN * KD;
        const __nv_bfloat16* kh = khi + (long)b * NN * KD;
        const __nv_bfloat16* kl = klo + (long)b * NN * KD;

        float acc[2][8][4];
        #pragma unroll
        for (int a = 0; a < 2; a++)
            #pragma unroll
            for (int bb = 0; bb < 8; bb++)
                #pragma unroll
                for (int c = 0; c < 4; c++) acc[a][bb][c] = 0.f;

        const uint32_t aOff = (uint32_t)(wm * 32 + (lane & 15)) * ROWB + (lane >> 4) * 16;
        const uint32_t bOff = (uint32_t)(wn * 64 + (lane & 15)) * ROWB + (lane >> 4) * 16;

        auto load_stage = [&](int kt, int stg) {
            const uint32_t sb = s0 + OFF_PIPE + (uint32_t)stg * SSTRIDE;
            #pragma unroll
            for (int it = 0; it < 4; it++) {
                int r = lrow + it * 32;
                long gsrc = (long)r * KD + kt * 64 + lq * 8;
                uint32_t sdst = (uint32_t)r * ROWB + lq * 16;
                CP16(sb + 0 * TILE_B + sdst, qh + gsrc);
                CP16(sb + 1 * TILE_B + sdst, ql + gsrc);
                CP16(sb + 2 * TILE_B + sdst, kh + gsrc);
                CP16(sb + 3 * TILE_B + sdst, kl + gsrc);
            }
            CP_COMMIT();
        };

        load_stage(0, 0);
        for (int kt = 0; kt < 8; kt++) {
            if (kt < 7) { load_stage(kt + 1, (kt + 1) & 1); CP_WAIT1(); }
            else        { CP_WAIT0(); }
            __syncthreads();

            const uint32_t sb  = s0 + OFF_PIPE + (uint32_t)(kt & 1) * SSTRIDE;
            const uint32_t sQh = sb;
            const uint32_t sQl = sb + TILE_B;
            const uint32_t sKh = sb + 2 * TILE_B;
            const uint32_t sKl = sb + 3 * TILE_B;

            #pragma unroll
            for (int ks = 0; ks < 4; ks++) {
                const uint32_t kByte = ks * 32;
                uint32_t Bf[16], Af[8], Af2[8];
                #pragma unroll
                for (int c = 0; c < 4; c++) {
                    uint32_t ad = sKh + bOff + (uint32_t)c * (16 * ROWB) + kByte;
                    LDSM4(Bf[c*4+0], Bf[c*4+1], Bf[c*4+2], Bf[c*4+3], ad);
                }
                #pragma unroll
                for (int mt = 0; mt < 2; mt++) {
                    uint32_t ad = sQh + aOff + (uint32_t)mt * (16 * ROWB) + kByte;
                    LDSM4(Af[mt*4+0], Af[mt*4+1], Af[mt*4+2], Af[mt*4+3], ad);
                }
                #pragma unroll
                for (int mt = 0; mt < 2; mt++) {
                    uint32_t ad = sQl + aOff + (uint32_t)mt * (16 * ROWB) + kByte;
                    LDSM4(Af2[mt*4+0], Af2[mt*4+1], Af2[mt*4+2], Af2[mt*4+3], ad);
                }
                #pragma unroll
                for (int mt = 0; mt < 2; mt++)
                    #pragma unroll
                    for (int c = 0; c < 4; c++) {
                        MMA16816(acc[mt][c*2+0], Af[mt*4+0], Af[mt*4+1], Af[mt*4+2], Af[mt*4+3],
                                 Bf[c*4+0], Bf[c*4+2]);
                        MMA16816(acc[mt][c*2+1], Af[mt*4+0], Af[mt*4+1], Af[mt*4+2], Af[mt*4+3],
                                 Bf[c*4+1], Bf[c*4+3]);
                        MMA16816(acc[mt][c*2+0], Af2[mt*4+0], Af2[mt*4+1], Af2[mt*4+2], Af2[mt*4+3],
                                 Bf[c*4+0], Bf[c*4+2]);
                        MMA16816(acc[mt][c*2+1], Af2[mt*4+0], Af2[mt*4+1], Af2[mt*4+2], Af2[mt*4+3],
                                 Bf[c*4+1], Bf[c*4+3]);
                    }
                #pragma unroll
                for (int c = 0; c < 4; c++) {
                    uint32_t ad = sKl + bOff + (uint32_t)c * (16 * ROWB) + kByte;
                    LDSM4(Bf[c*4+0], Bf[c*4+1], Bf[c*4+2], Bf[c*4+3], ad);
                }
                #pragma unroll
                for (int mt = 0; mt < 2; mt++)
                    #pragma unroll
                    for (int c = 0; c < 4; c++) {
                        MMA16816(acc[mt][c*2+0], Af[mt*4+0], Af[mt*4+1], Af[mt*4+2], Af[mt*4+3],
                                 Bf[c*4+0], Bf[c*4+2]);
                        MMA16816(acc[mt][c*2+1], Af[mt*4+0], Af[mt*4+1], Af[mt*4+2], Af[mt*4+3],
                                 Bf[c*4+1], Bf[c*4+3]);
                    }
            }
            __syncthreads();
        }
        // scores -> smem fp32
        #pragma unroll
        for (int mt = 0; mt < 2; mt++) {
            int r0 = wm * 32 + mt * 16 + group;
            int r1 = r0 + 8;
            #pragma unroll
            for (int nt = 0; nt < 8; nt++) {
                int col = wn * 64 + (nt >> 1) * 16 + (nt & 1) * 8 + tig * 2;
                *(float2*)(s_sc + r0 * 128 + col) = make_float2(acc[mt][nt][0], acc[mt][nt][1]);
                *(float2*)(s_sc + r1 * 128 + col) = make_float2(acc[mt][nt][2], acc[mt][nt][3]);
            }
        }
    }
    __syncthreads();

    // ---------------- phase 2: masked softmax ----------------
    {
        const float* mb = mask + (long)b * NN * NN;
        float* attb = att + (long)b * NN * NN;
        for (int r = 0; r < 16; r++) {
            int row = wid * 16 + r;
            float vals[4];
            float mx = -1e30f;
            #pragma unroll
            for (int c = 0; c < 4; c++) {
                int col = lane + c * 32;
                float m  = mb[row * 128 + col];
                float sc = s_sc[row * 128 + col];
                float vv = sc * m - 1000.0f * (1.0f - m);
                vals[c] = vv;
                mx = fmaxf(mx, vv);
            }
            #pragma unroll
            for (int off = 16; off; off >>= 1)
                mx = fmaxf(mx, __shfl_xor_sync(0xffffffffu, mx, off));
            float sum = 0.f;
            #pragma unroll
            for (int c = 0; c < 4; c++) {
                vals[c] = __expf(vals[c] - mx);
                sum += vals[c];
            }
            #pragma unroll
            for (int off = 16; off; off >>= 1)
                sum += __shfl_xor_sync(0xffffffffu, sum, off);
            float inv = 1.0f / sum;
            #pragma unroll
            for (int c = 0; c < 4; c++) {
                int col = lane + c * 32;
                float p = vals[c] * inv;
                attb[row * 128 + col] = p;
                __nv_bfloat16 h, l;
                split_bf16(p, h, l);
                *(__nv_bfloat16*)(sm + OFF_PHI + row * ROWP + col * 2) = h;
                *(__nv_bfloat16*)(sm + OFF_PLO + row * ROWP + col * 2) = l;
            }
        }
    }

    // ---------------- phase 3: ctx = P @ v ----------------
    {
        const __nv_bfloat16* vhb = vhi + (long)b * NN * HID;
        const __nv_bfloat16* vlb = vlo + (long)b * NN * HID;
        __nv_bfloat16* chb = ctxhi + (long)b * NN * HID;
        __nv_bfloat16* clb = ctxlo + (long)b * NN * HID;

        const uint32_t sPh = s0 + OFF_PHI;
        const uint32_t sPl = s0 + OFF_PLO;
        const uint32_t sVh = s0 + OFF_VTH;
        const uint32_t sVl = s0 + OFF_VTL;

        const uint32_t aOffP = (uint32_t)(wm * 32 + (lane & 15)) * ROWP + (lane >> 4) * 16;
        const uint32_t bOffV = (uint32_t)(wn * 32 + (lane & 15)) * ROWP + (lane >> 4) * 16;

        for (int hc = 0; hc < 4; hc++) {
            __syncthreads();
            for (int idx = tid; idx < 64 * 128; idx += 256) {
                int node = idx >> 6;
                int h = idx & 63;
                __nv_bfloat16 a = vhb[(long)node * HID + hc * 64 + h];
                __nv_bfloat16 c = vlb[(long)node * HID + hc * 64 + h];
                *(__nv_bfloat16*)(sm + OFF_VTH + h * ROWP + node * 2) = a;
                *(__nv_bfloat16*)(sm + OFF_VTL + h * ROWP + node * 2) = c;
            }
            __syncthreads();

            float acc2[2][4][4];
            #pragma unroll
            for (int a = 0; a < 2; a++)
                #pragma unroll
                for (int bb = 0; bb < 4; bb++)
                    #pragma unroll
                    for (int c = 0; c < 4; c++) acc2[a][bb][c] = 0.f;

            #pragma unroll
            for (int ks = 0; ks < 8; ks++) {
                const uint32_t kByte = ks * 32;
                uint32_t Bf[8], Af[8], Af2[8];
                #pragma unroll
                for (int c = 0; c < 2; c++) {
                    uint32_t ad = sVh + bOffV + (uint32_t)c * (16 * ROWP) + kByte;
                    LDSM4(Bf[c*4+0], Bf[c*4+1], Bf[c*4+2], Bf[c*4+3], ad);
                }
                #pragma unroll
                for (int mt = 0; mt < 2; mt++) {
                    uint32_t ad = sPh + aOffP + (uint32_t)mt * (16 * ROWP) + kByte;
                    LDSM4(Af[mt*4+0], Af[mt*4+1], Af[mt*4+2], Af[mt*4+3], ad);
                }
                #pragma unroll
                for (int mt = 0; mt < 2; mt++) {
                    uint32_t ad = sPl + aOffP + (uint32_t)mt * (16 * ROWP) + kByte;
                    LDSM4(Af2[mt*4+0], Af2[mt*4+1], Af2[mt*4+2], Af2[mt*4+3], ad);
                }
                #pragma unroll
                for (int mt = 0; mt < 2; mt++)
                    #pragma unroll
                    for (int c = 0; c < 2; c++) {
                        MMA16816(acc2[mt][c*2+0], Af[mt*4+0], Af[mt*4+1], Af[mt*4+2], Af[mt*4+3],
                                 Bf[c*4+0], Bf[c*4+2]);
                        MMA16816(acc2[mt][c*2+1], Af[mt*4+0], Af[mt*4+1], Af[mt*4+2], Af[mt*4+3],
                                 Bf[c*4+1], Bf[c*4+3]);
                        MMA16816(acc2[mt][c*2+0], Af2[mt*4+0], Af2[mt*4+1], Af2[mt*4+2], Af2[mt*4+3],
                                 Bf[c*4+0], Bf[c*4+2]);
                        MMA16816(acc2[mt][c*2+1], Af2[mt*4+0], Af2[mt*4+1], Af2[mt*4+2], Af2[mt*4+3],
                                 Bf[c*4+1], Bf[c*4+3]);
                    }
                #pragma unroll
                for (int c = 0; c < 2; c++) {
                    uint32_t ad = sVl + bOffV + (uint32_t)c * (16 * ROWP) + kByte;
                    LDSM4(Bf[c*4+0], Bf[c*4+1], Bf[c*4+2], Bf[c*4+3], ad);
                }
                #pragma unroll
                for (int mt = 0; mt < 2; mt++)
                    #pragma unroll
                    for (int c = 0; c < 2; c++) {
                        MMA16816(acc2[mt][c*2+0], Af[mt*4+0], Af[mt*4+1], Af[mt*4+2], Af[mt*4+3],
                                 Bf[c*4+0], Bf[c*4+2]);
                        MMA16816(acc2[mt][c*2+1], Af[mt*4+0], Af[mt*4+1], Af[mt*4+2], Af[mt*4+3],
                                 Bf[c*4+1], Bf[c*4+3]);
                    }
            }

            #pragma unroll
            for (int mt = 0; mt < 2; mt++) {
                int r0 = wm * 32 + mt * 16 + group;
                int r1 = r0 + 8;
                #pragma unroll
                for (int nt = 0; nt < 4; nt++) {
                    int col = hc * 64 + wn * 32 + (nt >> 1) * 16 + (nt & 1) * 8 + tig * 2;
                    __nv_bfloat16 h00, l00, h01, l01, h10, l10, h11, l11;
                    split_bf16(acc2[mt][nt][0], h00, l00);
                    split_bf16(acc2[mt][nt][1], h01, l01);
                    split_bf16(acc2[mt][nt][2], h10, l10);
                    split_bf16(acc2[mt][nt][3], h11, l11);
                    *(__nv_bfloat162*)(chb + (long)r0 * HID + col) = __halves2bfloat162(h00, h01);
                    *(__nv_bfloat162*)(clb + (long)r0 * HID + col) = __halves2bfloat162(l00, l01);
                    *(__nv_bfloat162*)(chb + (long)r1 * HID + col) = __halves2bfloat162(h10, h11);
                    *(__nv_bfloat162*)(clb + (long)r1 * HID + col) = __halves2bfloat162(l10, l11);
                }
            }
        }
    }
}

// =====================================================================
extern "C" void kernel_launch(void* const* d_in, const int* in_sizes, int n_in,
                              void* d_out, int out_size)
{
    const float* x    = (const float*)d_in[0];
    const float* mask = (const float*)d_in[1];
    const float* Wv   = (const float*)d_in[2];
    const float* bv   = (const float*)d_in[3];
    const float* Wq   = (const float*)d_in[4];
    const float* bq   = (const float*)d_in[5];
    const float* Wk   = (const float*)d_in[6];
    const float* bk   = (const float*)d_in[7];
    const float* Wo   = (const float*)d_in[8];
    const float* bo   = (const float*)d_in[9];

    float* out = (float*)d_out;

    float* pattd;
    cudaGetSymbolAddress((void**)&pattd, g_att_dummy);

    __nv_bfloat16 *xhi, *xlo, *qhi, *qlo, *khi, *klo, *vhi, *vlo, *chi, *clo;
    cudaGetSymbolAddress((void**)&xhi, g_xhi);
    cudaGetSymbolAddress((void**)&xlo, g_xlo);
    cudaGetSymbolAddress((void**)&qhi, g_qhi);
    cudaGetSymbolAddress((void**)&qlo, g_qlo);
    cudaGetSymbolAddress((void**)&khi, g_khi);
    cudaGetSymbolAddress((void**)&klo, g_klo);
    cudaGetSymbolAddress((void**)&vhi, g_vhi);
    cudaGetSymbolAddress((void**)&vlo, g_vlo);
    cudaGetSymbolAddress((void**)&chi, g_chi);
    cudaGetSymbolAddress((void**)&clo, g_clo);

    __nv_bfloat16 *wvhi, *wvlo, *wqhi, *wqlo, *wkhi, *wklo, *wohi, *wolo;
    cudaGetSymbolAddress((void**)&wvhi, g_wvhi);
    cudaGetSymbolAddress((void**)&wvlo, g_wvlo);
    cudaGetSymbolAddress((void**)&wqhi, g_wqhi);
    cudaGetSymbolAddress((void**)&wqlo, g_wqlo);
    cudaGetSymbolAddress((void**)&wkhi, g_wkhi);
    cudaGetSymbolAddress((void**)&wklo, g_wklo);
    cudaGetSymbolAddress((void**)&wohi, g_wohi);
    cudaGetSymbolAddress((void**)&wolo, g_wolo);

    float* patt = ((long)out_size >= TOT_ELEMS) ? (out + OUT_ELEMS) : pattd;

    cudaFuncSetAttribute(attention_mma,
                         cudaFuncAttributeMaxDynamicSharedMemorySize, ATT_SMEM);
    cudaFuncSetAttribute(mma_gemm,
                         cudaFuncAttributeMaxDynamicSharedMemorySize, GEMM_SMEM);

    {
        long n4 = (long)MROWS * GK / 4;
        split_x_kernel<<<(unsigned)((n4 + 255) / 256), 256>>>(
            (const float4*)x, (uint2*)xhi, (uint2*)xlo, n4);
    }
    prep_weight<<<(GK*HID  + 255)/256, 256>>>(Wv, wvhi, wvlo, GK, HID);
    prep_weight<<<(GK*KD   + 255)/256, 256>>>(Wq, wqhi, wqlo, GK, KD);
    prep_weight<<<(GK*KD   + 255)/256, 256>>>(Wk, wkhi, wklo, GK, KD);
    prep_weight<<<(HID*DOUT+ 255)/256, 256>>>(Wo, wohi, wolo, HID, DOUT);

    const int mTiles = MROWS / 128;
    mma_gemm<<<dim3(HID/128, mTiles), 256, GEMM_SMEM>>>(
        xhi, xlo, wvhi, wvlo, bv, nullptr, vhi, vlo, HID, 1);
    mma_gemm<<<dim3(KD/128,  mTiles), 256, GEMM_SMEM>>>(
        xhi, xlo, wqhi, wqlo, bq, nullptr, qhi, qlo, KD, 1);
    mma_gemm<<<dim3(KD/128,  mTiles), 256, GEMM_SMEM>>>(
        xhi, xlo, wkhi, wklo, bk, nullptr, khi, klo, KD, 1);

    attention_mma<<<BATCH, 256, ATT_SMEM>>>(qhi, qlo, khi, klo, vhi, vlo,
                                            mask, patt, chi, clo);

    mma_gemm<<<dim3(DOUT/128, mTiles), 256, GEMM_SMEM>>>(
        chi, clo, wohi, wolo, bo, out, nullptr, nullptr, DOUT, 0);
}

// round 6
// speedup vs baseline: 1.0443x; 1.0443x over previous
#include <cuda_runtime.h>
#include <cuda_bf16.h>
#include <cstdint>

// ---------------- problem constants ----------------
#define BATCH 1024
#define NN    128
#define DIN   256
#define HID   256
#define DOUT  256
#define KD    512
#define MROWS (BATCH*NN)
#define GK    256

#define OUT_ELEMS ((long)MROWS*DOUT)
#define ATT_ELEMS ((long)BATCH*NN*NN)
#define TOT_ELEMS (OUT_ELEMS + ATT_ELEMS)

// ---------------- scratch ----------------
__device__ __align__(16) float g_att_dummy[ATT_ELEMS];

__device__ __align__(16) __nv_bfloat16 g_xhi[(long)MROWS*GK];
__device__ __align__(16) __nv_bfloat16 g_xlo[(long)MROWS*GK];
__device__ __align__(16) __nv_bfloat16 g_qhi[(long)MROWS*KD];
__device__ __align__(16) __nv_bfloat16 g_qlo[(long)MROWS*KD];
__device__ __align__(16) __nv_bfloat16 g_khi[(long)MROWS*KD];
__device__ __align__(16) __nv_bfloat16 g_klo[(long)MROWS*KD];
__device__ __align__(16) __nv_bfloat16 g_vhi[(long)MROWS*HID];
__device__ __align__(16) __nv_bfloat16 g_vlo[(long)MROWS*HID];
__device__ __align__(16) __nv_bfloat16 g_chi[(long)MROWS*HID];
__device__ __align__(16) __nv_bfloat16 g_clo[(long)MROWS*HID];

__device__ __align__(16) __nv_bfloat16 g_wvhi[GK*HID], g_wvlo[GK*HID];
__device__ __align__(16) __nv_bfloat16 g_wqhi[GK*KD],  g_wqlo[GK*KD];
__device__ __align__(16) __nv_bfloat16 g_wkhi[GK*KD],  g_wklo[GK*KD];
__device__ __align__(16) __nv_bfloat16 g_wohi[HID*DOUT], g_wolo[HID*DOUT];

// ---------------- helpers ----------------
__device__ __forceinline__ uint32_t smem_u32(const void* p) {
    uint32_t a;
    asm("{ .reg .u64 t; cvta.to.shared.u64 t, %1; cvt.u32.u64 %0, t; }" : "=r"(a) : "l"(p));
    return a;
}
__device__ __forceinline__ void split_bf16(float a, __nv_bfloat16& h, __nv_bfloat16& l) {
    h = __float2bfloat16_rn(a);
    l = __float2bfloat16_rn(a - __bfloat162float(h));
}

#define LDSM4(r0, r1, r2, r3, addr) \
    asm volatile("ldmatrix.sync.aligned.m8n8.x4.shared.b16 {%0,%1,%2,%3}, [%4];" \
                 : "=r"(r0), "=r"(r1), "=r"(r2), "=r"(r3) : "r"(addr))

#define MMA16816(d, a0, a1, a2, a3, b0, b1) \
    asm volatile("mma.sync.aligned.m16n8k16.row.col.f32.bf16.bf16.f32 " \
                 "{%0,%1,%2,%3},{%4,%5,%6,%7},{%8,%9},{%0,%1,%2,%3};" \
                 : "+f"((d)[0]), "+f"((d)[1]), "+f"((d)[2]), "+f"((d)[3]) \
                 : "r"(a0), "r"(a1), "r"(a2), "r"(a3), "r"(b0), "r"(b1))

#define CP16(saddr, gptr) \
    asm volatile("cp.async.cg.shared.global [%0], [%1], 16;" :: "r"(saddr), "l"(gptr))
#define CP_COMMIT() asm volatile("cp.async.commit_group;" ::: "memory")
#define CP_WAIT1()  asm volatile("cp.async.wait_group 1;" ::: "memory")
#define CP_WAIT0()  asm volatile("cp.async.wait_group 0;" ::: "memory")

// ---------------- prep kernels ----------------
__global__ void split_x_kernel(const float4* __restrict__ x,
                               uint2* __restrict__ hi, uint2* __restrict__ lo, long n4) {
    long i = (long)blockIdx.x * blockDim.x + threadIdx.x;
    if (i >= n4) return;
    float4 a = x[i];
    __nv_bfloat16 h0, l0, h1, l1, h2, l2, h3, l3;
    split_bf16(a.x, h0, l0); split_bf16(a.y, h1, l1);
    split_bf16(a.z, h2, l2); split_bf16(a.w, h3, l3);
    __nv_bfloat162 hA = __halves2bfloat162(h0, h1), hB = __halves2bfloat162(h2, h3);
    __nv_bfloat162 lA = __halves2bfloat162(l0, l1), lB = __halves2bfloat162(l2, l3);
    hi[i] = make_uint2(*(uint32_t*)&hA, *(uint32_t*)&hB);
    lo[i] = make_uint2(*(uint32_t*)&lA, *(uint32_t*)&lB);
}

__global__ void prep_weight(const float* __restrict__ W, __nv_bfloat16* __restrict__ hi,
                            __nv_bfloat16* __restrict__ lo, int K, int N) {
    int idx = blockIdx.x * 256 + threadIdx.x;
    if (idx >= K * N) return;
    int k = idx / N, n = idx % N;
    __nv_bfloat16 h, l;
    split_bf16(W[idx], h, l);
    hi[(long)n * K + k] = h;
    lo[(long)n * K + k] = l;
}

// =====================================================================
// bf16x3 mma GEMM. CTA 128x128, K=256 in 4 tiles of 64, 8 warps (4m x 2n).
// A (DRAM stream) double-buffered via cp.async; B (L2-hot weights) blocking.
// smem = 2*(A hi+lo) + (B hi+lo) = 110592 bytes -> occupancy 2.
// =====================================================================
#define ROWB 144
#define TILE_B (128 * ROWB)          // 18432
#define A_STAGE (2 * TILE_B)         // hi + lo
#define OFF_B (2 * A_STAGE)          // 73728
#define GEMM_SMEM (OFF_B + 2 * TILE_B)   // 110592

__global__ void __launch_bounds__(256, 2) mma_gemm(
    const __nv_bfloat16* __restrict__ Ahi, const __nv_bfloat16* __restrict__ Alo,
    const __nv_bfloat16* __restrict__ Bhi, const __nv_bfloat16* __restrict__ Blo,
    const float* __restrict__ bias, float* __restrict__ C,
    __nv_bfloat16* __restrict__ Chi, __nv_bfloat16* __restrict__ Clo,
    int Ncols, int mode)
{
    extern __shared__ char smc[];
    const uint32_t s0 = smem_u32(smc);

    const int tid  = threadIdx.x;
    const int wid  = tid >> 5;
    const int lane = tid & 31;
    const int wm   = wid >> 1;
    const int wn   = wid & 1;

    const long mBase = (long)blockIdx.y * 128;
    const int  nBase = blockIdx.x * 128;

    const __nv_bfloat16* Ah = Ahi + mBase * GK;
    const __nv_bfloat16* Al = Alo + mBase * GK;
    const __nv_bfloat16* Bh = Bhi + (long)nBase * GK;
    const __nv_bfloat16* Bl = Blo + (long)nBase * GK;

    float acc[2][8][4];
    #pragma unroll
    for (int a = 0; a < 2; a++)
        #pragma unroll
        for (int b = 0; b < 8; b++)
            #pragma unroll
            for (int c = 0; c < 4; c++) acc[a][b][c] = 0.f;

    const int lrow = tid >> 3;
    const int lq   = tid & 7;
    const uint32_t aOff = (uint32_t)(wm * 32 + (lane & 15)) * ROWB + (lane >> 4) * 16;
    const uint32_t bOff = (uint32_t)(wn * 64 + (lane & 15)) * ROWB + (lane >> 4) * 16;

    // async A stage loader: 8 cp.async per thread
    auto load_stageA = [&](int kt, int stg) {
        const uint32_t sb = s0 + (uint32_t)stg * A_STAGE;
        #pragma unroll
        for (int it = 0; it < 4; it++) {
            int r = lrow + it * 32;
            long gsrc = (long)r * GK + kt * 64 + lq * 8;
            uint32_t sdst = (uint32_t)r * ROWB + lq * 16;
            CP16(sb + sdst, Ah + gsrc);
            CP16(sb + TILE_B + sdst, Al + gsrc);
        }
        CP_COMMIT();
    };

    load_stageA(0, 0);
    for (int kt = 0; kt < 4; kt++) {
        __syncthreads();   // previous compute done: safe to overwrite B + A stage kt+1
        // blocking B load (L2-hot weights)
        #pragma unroll
        for (int it = 0; it < 4; it++) {
            int r = lrow + it * 32;
            long gsrc = (long)r * GK + kt * 64 + lq * 8;
            uint32_t sdst = (uint32_t)r * ROWB + lq * 16;
            *(uint4*)(smc + OFF_B + sdst)          = *(const uint4*)(Bh + gsrc);
            *(uint4*)(smc + OFF_B + TILE_B + sdst) = *(const uint4*)(Bl + gsrc);
        }
        if (kt < 3) { load_stageA(kt + 1, (kt + 1) & 1); CP_WAIT1(); }
        else        { CP_WAIT0(); }
        __syncthreads();

        const uint32_t sAh = s0 + (uint32_t)(kt & 1) * A_STAGE;
        const uint32_t sAl = sAh + TILE_B;
        const uint32_t sBh = s0 + OFF_B;
        const uint32_t sBl = sBh + TILE_B;

        #pragma unroll
        for (int ks = 0; ks < 4; ks++) {
            const uint32_t kByte = ks * 32;
            uint32_t Bf[16], Af[8], Af2[8];
            #pragma unroll
            for (int c = 0; c < 4; c++) {
                uint32_t ad = sBh + bOff + (uint32_t)c * (16 * ROWB) + kByte;
                LDSM4(Bf[c*4+0], Bf[c*4+1], Bf[c*4+2], Bf[c*4+3], ad);
            }
            #pragma unroll
            for (int mt = 0; mt < 2; mt++) {
                uint32_t ad = sAh + aOff + (uint32_t)mt * (16 * ROWB) + kByte;
                LDSM4(Af[mt*4+0], Af[mt*4+1], Af[mt*4+2], Af[mt*4+3], ad);
            }
            #pragma unroll
            for (int mt = 0; mt < 2; mt++) {
                uint32_t ad = sAl + aOff + (uint32_t)mt * (16 * ROWB) + kByte;
                LDSM4(Af2[mt*4+0], Af2[mt*4+1], Af2[mt*4+2], Af2[mt*4+3], ad);
            }
            #pragma unroll
            for (int mt = 0; mt < 2; mt++)
                #pragma unroll
                for (int c = 0; c < 4; c++) {
                    MMA16816(acc[mt][c*2+0], Af[mt*4+0], Af[mt*4+1], Af[mt*4+2], Af[mt*4+3],
                             Bf[c*4+0], Bf[c*4+2]);
                    MMA16816(acc[mt][c*2+1], Af[mt*4+0], Af[mt*4+1], Af[mt*4+2], Af[mt*4+3],
                             Bf[c*4+1], Bf[c*4+3]);
                    MMA16816(acc[mt][c*2+0], Af2[mt*4+0], Af2[mt*4+1], Af2[mt*4+2], Af2[mt*4+3],
                             Bf[c*4+0], Bf[c*4+2]);
                    MMA16816(acc[mt][c*2+1], Af2[mt*4+0], Af2[mt*4+1], Af2[mt*4+2], Af2[mt*4+3],
                             Bf[c*4+1], Bf[c*4+3]);
                }
            #pragma unroll
            for (int c = 0; c < 4; c++) {
                uint32_t ad = sBl + bOff + (uint32_t)c * (16 * ROWB) + kByte;
                LDSM4(Bf[c*4+0], Bf[c*4+1], Bf[c*4+2], Bf[c*4+3], ad);
            }
            #pragma unroll
            for (int mt = 0; mt < 2; mt++)
                #pragma unroll
                for (int c = 0; c < 4; c++) {
                    MMA16816(acc[mt][c*2+0], Af[mt*4+0], Af[mt*4+1], Af[mt*4+2], Af[mt*4+3],
                             Bf[c*4+0], Bf[c*4+2]);
                    MMA16816(acc[mt][c*2+1], Af[mt*4+0], Af[mt*4+1], Af[mt*4+2], Af[mt*4+3],
                             Bf[c*4+1], Bf[c*4+3]);
                }
        }
    }

    const int group = lane >> 2;
    const int tig   = lane & 3;
    #pragma unroll
    for (int mt = 0; mt < 2; mt++) {
        long r0 = mBase + wm * 32 + mt * 16 + group;
        long r1 = r0 + 8;
        #pragma unroll
        for (int nt = 0; nt < 8; nt++) {
            int col = nBase + wn * 64 + (nt >> 1) * 16 + (nt & 1) * 8 + tig * 2;
            float b0 = bias[col], b1 = bias[col + 1];
            float v00 = fmaxf(acc[mt][nt][0] + b0, 0.f);
            float v01 = fmaxf(acc[mt][nt][1] + b1, 0.f);
            float v10 = fmaxf(acc[mt][nt][2] + b0, 0.f);
            float v11 = fmaxf(acc[mt][nt][3] + b1, 0.f);
            if (mode == 0) {
                *(float2*)(C + r0 * Ncols + col) = make_float2(v00, v01);
                *(float2*)(C + r1 * Ncols + col) = make_float2(v10, v11);
            } else {
                __nv_bfloat16 h00, l00, h01, l01, h10, l10, h11, l11;
                split_bf16(v00, h00, l00); split_bf16(v01, h01, l01);
                split_bf16(v10, h10, l10); split_bf16(v11, h11, l11);
                *(__nv_bfloat162*)(Chi + r0 * Ncols + col) = __halves2bfloat162(h00, h01);
                *(__nv_bfloat162*)(Clo + r0 * Ncols + col) = __halves2bfloat162(l00, l01);
                *(__nv_bfloat162*)(Chi + r1 * Ncols + col) = __halves2bfloat162(h10, h11);
                *(__nv_bfloat162*)(Clo + r1 * Ncols + col) = __halves2bfloat162(l10, l11);
            }
        }
    }
}

// =====================================================================
// Fused attention, all-HMMA (R4 proven version).
// =====================================================================
#define ROWP 272
#define OFF_PHI 65536
#define OFF_PLO 100352
#define OFF_VTH 135168
#define OFF_VTL 152576
#define ATT_SMEM 169984

__global__ void __launch_bounds__(256, 1) attention_mma(
    const __nv_bfloat16* __restrict__ qhi, const __nv_bfloat16* __restrict__ qlo,
    const __nv_bfloat16* __restrict__ khi, const __nv_bfloat16* __restrict__ klo,
    const __nv_bfloat16* __restrict__ vhi, const __nv_bfloat16* __restrict__ vlo,
    const float* __restrict__ mask, float* __restrict__ att,
    __nv_bfloat16* __restrict__ ctxhi, __nv_bfloat16* __restrict__ ctxlo)
{
    extern __shared__ char sm[];
    float* s_sc = (float*)sm;
    const uint32_t s0 = smem_u32(sm);

    const int b    = blockIdx.x;
    const int tid  = threadIdx.x;
    const int wid  = tid >> 5;
    const int lane = tid & 31;
    const int wm   = wid >> 1;
    const int wn   = wid & 1;
    const int lrow = tid >> 3;
    const int lq   = tid & 7;
    const int group = lane >> 2;
    const int tig   = lane & 3;

    // ---------------- phase 1: S = q @ k^T ----------------
    {
        const __nv_bfloat16* qh = qhi + (long)b * NN * KD;
        const __nv_bfloat16* ql = qlo + (long)b * NN * KD;
        const __nv_bfloat16* kh = khi + (long)b * NN * KD;
        const __nv_bfloat16* kl = klo + (long)b * NN * KD;

        const uint32_t sQh = s0 + 65536;
        const uint32_t sQl = sQh + TILE_B;
        const uint32_t sKh = sQh + 2 * TILE_B;
        const uint32_t sKl = sQh + 3 * TILE_B;

        float acc[2][8][4];
        #pragma unroll
        for (int a = 0; a < 2; a++)
            #pragma unroll
            for (int bb = 0; bb < 8; bb++)
                #pragma unroll
                for (int c = 0; c < 4; c++) acc[a][bb][c] = 0.f;

        const uint32_t aOff = (uint32_t)(wm * 32 + (lane & 15)) * ROWB + (lane >> 4) * 16;
        const uint32_t bOff = (uint32_t)(wn * 64 + (lane & 15)) * ROWB + (lane >> 4) * 16;

        for (int kt = 0; kt < 8; kt++) {
            __syncthreads();
            #pragma unroll
            for (int it = 0; it < 4; it++) {
                int r = lrow + it * 32;
                long gsrc = (long)r * KD + kt * 64 + lq * 8;
                uint32_t sdst = (uint32_t)r * ROWB + lq * 16;
                *(uint4*)(sm + 65536 + 0 * TILE_B + sdst) = *(const uint4*)(qh + gsrc);
                *(uint4*)(sm + 65536 + 1 * TILE_B + sdst) = *(const uint4*)(ql + gsrc);
                *(uint4*)(sm + 65536 + 2 * TILE_B + sdst) = *(const uint4*)(kh + gsrc);
                *(uint4*)(sm + 65536 + 3 * TILE_B + sdst) = *(const uint4*)(kl + gsrc);
            }
            __syncthreads();

            #pragma unroll
            for (int ks = 0; ks < 4; ks++) {
                const uint32_t kByte = ks * 32;
                uint32_t Bf[16], Af[8], Af2[8];
                #pragma unroll
                for (int c = 0; c < 4; c++) {
                    uint32_t ad = sKh + bOff + (uint32_t)c * (16 * ROWB) + kByte;
                    LDSM4(Bf[c*4+0], Bf[c*4+1], Bf[c*4+2], Bf[c*4+3], ad);
                }
                #pragma unroll
                for (int mt = 0; mt < 2; mt++) {
                    uint32_t ad = sQh + aOff + (uint32_t)mt * (16 * ROWB) + kByte;
                    LDSM4(Af[mt*4+0], Af[mt*4+1], Af[mt*4+2], Af[mt*4+3], ad);
                }
                #pragma unroll
                for (int mt = 0; mt < 2; mt++) {
                    uint32_t ad = sQl + aOff + (uint32_t)mt * (16 * ROWB) + kByte;
                    LDSM4(Af2[mt*4+0], Af2[mt*4+1], Af2[mt*4+2], Af2[mt*4+3], ad);
                }
                #pragma unroll
                for (int mt = 0; mt < 2; mt++)
                    #pragma unroll
                    for (int c = 0; c < 4; c++) {
                        MMA16816(acc[mt][c*2+0], Af[mt*4+0], Af[mt*4+1], Af[mt*4+2], Af[mt*4+3],
                                 Bf[c*4+0], Bf[c*4+2]);
                        MMA16816(acc[mt][c*2+1], Af[mt*4+0], Af[mt*4+1], Af[mt*4+2], Af[mt*4+3],
                                 Bf[c*4+1], Bf[c*4+3]);
                        MMA16816(acc[mt][c*2+0], Af2[mt*4+0], Af2[mt*4+1], Af2[mt*4+2], Af2[mt*4+3],
                                 Bf[c*4+0], Bf[c*4+2]);
                        MMA16816(acc[mt][c*2+1], Af2[mt*4+0], Af2[mt*4+1], Af2[mt*4+2], Af2[mt*4+3],
                                 Bf[c*4+1], Bf[c*4+3]);
                    }
                #pragma unroll
                for (int c = 0; c < 4; c++) {
                    uint32_t ad = sKl + bOff + (uint32_t)c * (16 * ROWB) + kByte;
                    LDSM4(Bf[c*4+0], Bf[c*4+1], Bf[c*4+2], Bf[c*4+3], ad);
                }
                #pragma unroll
                for (int mt = 0; mt < 2; mt++)
                    #pragma unroll
                    for (int c = 0; c < 4; c++) {
                        MMA16816(acc[mt][c*2+0], Af[mt*4+0], Af[mt*4+1], Af[mt*4+2], Af[mt*4+3],
                                 Bf[c*4+0], Bf[c*4+2]);
                        MMA16816(acc[mt][c*2+1], Af[mt*4+0], Af[mt*4+1], Af[mt*4+2], Af[mt*4+3],
                                 Bf[c*4+1], Bf[c*4+3]);
                    }
            }
        }
        __syncthreads();
        #pragma unroll
        for (int mt = 0; mt < 2; mt++) {
            int r0 = wm * 32 + mt * 16 + group;
            int r1 = r0 + 8;
            #pragma unroll
            for (int nt = 0; nt < 8; nt++) {
                int col = wn * 64 + (nt >> 1) * 16 + (nt & 1) * 8 + tig * 2;
                *(float2*)(s_sc + r0 * 128 + col) = make_float2(acc[mt][nt][0], acc[mt][nt][1]);
                *(float2*)(s_sc + r1 * 128 + col) = make_float2(acc[mt][nt][2], acc[mt][nt][3]);
            }
        }
    }
    __syncthreads();

    // ---------------- phase 2: masked softmax ----------------
    {
        const float* mb = mask + (long)b * NN * NN;
        float* attb = att + (long)b * NN * NN;
        for (int r = 0; r < 16; r++) {
            int row = wid * 16 + r;
            float vals[4];
            float mx = -1e30f;
            #pragma unroll
            for (int c = 0; c < 4; c++) {
                int col = lane + c * 32;
                float m  = mb[row * 128 + col];
                float sc = s_sc[row * 128 + col];
                float vv = sc * m - 1000.0f * (1.0f - m);
                vals[c] = vv;
                mx = fmaxf(mx, vv);
            }
            #pragma unroll
            for (int off = 16; off; off >>= 1)
                mx = fmaxf(mx, __shfl_xor_sync(0xffffffffu, mx, off));
            float sum = 0.f;
            #pragma unroll
            for (int c = 0; c < 4; c++) {
                vals[c] = __expf(vals[c] - mx);
                sum += vals[c];
            }
            #pragma unroll
            for (int off = 16; off; off >>= 1)
                sum += __shfl_xor_sync(0xffffffffu, sum, off);
            float inv = 1.0f / sum;
            #pragma unroll
            for (int c = 0; c < 4; c++) {
                int col = lane + c * 32;
                float p = vals[c] * inv;
                attb[row * 128 + col] = p;
                __nv_bfloat16 h, l;
                split_bf16(p, h, l);
                *(__nv_bfloat16*)(sm + OFF_PHI + row * ROWP + col * 2) = h;
                *(__nv_bfloat16*)(sm + OFF_PLO + row * ROWP + col * 2) = l;
            }
        }
    }

    // ---------------- phase 3: ctx = P @ v ----------------
    {
        const __nv_bfloat16* vhb = vhi + (long)b * NN * HID;
        const __nv_bfloat16* vlb = vlo + (long)b * NN * HID;
        __nv_bfloat16* chb = ctxhi + (long)b * NN * HID;
        __nv_bfloat16* clb = ctxlo + (long)b * NN * HID;

        const uint32_t sPh = s0 + OFF_PHI;
        const uint32_t sPl = s0 + OFF_PLO;
        const uint32_t sVh = s0 + OFF_VTH;
        const uint32_t sVl = s0 + OFF_VTL;

        const uint32_t aOffP = (uint32_t)(wm * 32 + (lane & 15)) * ROWP + (lane >> 4) * 16;
        const uint32_t bOffV = (uint32_t)(wn * 32 + (lane & 15)) * ROWP + (lane >> 4) * 16;

        for (int hc = 0; hc < 4; hc++) {
            __syncthreads();
            for (int idx = tid; idx < 64 * 128; idx += 256) {
                int node = idx >> 6;
                int h = idx & 63;
                __nv_bfloat16 a = vhb[(long)node * HID + hc * 64 + h];
                __nv_bfloat16 c = vlb[(long)node * HID + hc * 64 + h];
                *(__nv_bfloat16*)(sm + OFF_VTH + h * ROWP + node * 2) = a;
                *(__nv_bfloat16*)(sm + OFF_VTL + h * ROWP + node * 2) = c;
            }
            __syncthreads();

            float acc2[2][4][4];
            #pragma unroll
            for (int a = 0; a < 2; a++)
                #pragma unroll
                for (int bb = 0; bb < 4; bb++)
                    #pragma unroll
                    for (int c = 0; c < 4; c++) acc2[a][bb][c] = 0.f;

            #pragma unroll
            for (int ks = 0; ks < 8; ks++) {
                const uint32_t kByte = ks * 32;
                uint32_t Bf[8], Af[8], Af2[8];
                #pragma unroll
                for (int c = 0; c < 2; c++) {
                    uint32_t ad = sVh + bOffV + (uint32_t)c * (16 * ROWP) + kByte;
                    LDSM4(Bf[c*4+0], Bf[c*4+1], Bf[c*4+2], Bf[c*4+3], ad);
                }
                #pragma unroll
                for (int mt = 0; mt < 2; mt++) {
                    uint32_t ad = sPh + aOffP + (uint32_t)mt * (16 * ROWP) + kByte;
                    LDSM4(Af[mt*4+0], Af[mt*4+1], Af[mt*4+2], Af[mt*4+3], ad);
                }
                #pragma unroll
                for (int mt = 0; mt < 2; mt++) {
                    uint32_t ad = sPl + aOffP + (uint32_t)mt * (16 * ROWP) + kByte;
                    LDSM4(Af2[mt*4+0], Af2[mt*4+1], Af2[mt*4+2], Af2[mt*4+3], ad);
                }
                #pragma unroll
                for (int mt = 0; mt < 2; mt++)
                    #pragma unroll
                    for (int c = 0; c < 2; c++) {
                        MMA16816(acc2[mt][c*2+0], Af[mt*4+0], Af[mt*4+1], Af[mt*4+2], Af[mt*4+3],
                                 Bf[c*4+0], Bf[c*4+2]);
                        MMA16816(acc2[mt][c*2+1], Af[mt*4+0], Af[mt*4+1], Af[mt*4+2], Af[mt*4+3],
                                 Bf[c*4+1], Bf[c*4+3]);
                        MMA16816(acc2[mt][c*2+0], Af2[mt*4+0], Af2[mt*4+1], Af2[mt*4+2], Af2[mt*4+3],
                                 Bf[c*4+0], Bf[c*4+2]);
                        MMA16816(acc2[mt][c*2+1], Af2[mt*4+0], Af2[mt*4+1], Af2[mt*4+2], Af2[mt*4+3],
                                 Bf[c*4+1], Bf[c*4+3]);
                    }
                #pragma unroll
                for (int c = 0; c < 2; c++) {
                    uint32_t ad = sVl + bOffV + (uint32_t)c * (16 * ROWP) + kByte;
                    LDSM4(Bf[c*4+0], Bf[c*4+1], Bf[c*4+2], Bf[c*4+3], ad);
                }
                #pragma unroll
                for (int mt = 0; mt < 2; mt++)
                    #pragma unroll
                    for (int c = 0; c < 2; c++) {
                        MMA16816(acc2[mt][c*2+0], Af[mt*4+0], Af[mt*4+1], Af[mt*4+2], Af[mt*4+3],
                                 Bf[c*4+0], Bf[c*4+2]);
                        MMA16816(acc2[mt][c*2+1], Af[mt*4+0], Af[mt*4+1], Af[mt*4+2], Af[mt*4+3],
                                 Bf[c*4+1], Bf[c*4+3]);
                    }
            }

            #pragma unroll
            for (int mt = 0; mt < 2; mt++) {
                int r0 = wm * 32 + mt * 16 + group;
                int r1 = r0 + 8;
                #pragma unroll
                for (int nt = 0; nt < 4; nt++) {
                    int col = hc * 64 + wn * 32 + (nt >> 1) * 16 + (nt & 1) * 8 + tig * 2;
                    __nv_bfloat16 h00, l00, h01, l01, h10, l10, h11, l11;
                    split_bf16(acc2[mt][nt][0], h00, l00);
                    split_bf16(acc2[mt][nt][1], h01, l01);
                    split_bf16(acc2[mt][nt][2], h10, l10);
                    split_bf16(acc2[mt][nt][3], h11, l11);
                    *(__nv_bfloat162*)(chb + (long)r0 * HID + col) = __halves2bfloat162(h00, h01);
                    *(__nv_bfloat162*)(clb + (long)r0 * HID + col) = __halves2bfloat162(l00, l01);
                    *(__nv_bfloat162*)(chb + (long)r1 * HID + col) = __halves2bfloat162(h10, h11);
                    *(__nv_bfloat162*)(clb + (long)r1 * HID + col) = __halves2bfloat162(l10, l11);
                }
            }
        }
    }
}

// =====================================================================
extern "C" void kernel_launch(void* const* d_in, const int* in_sizes, int n_in,
                              void* d_out, int out_size)
{
    const float* x    = (const float*)d_in[0];
    const float* mask = (const float*)d_in[1];
    const float* Wv   = (const float*)d_in[2];
    const float* bv   = (const float*)d_in[3];
    const float* Wq   = (const float*)d_in[4];
    const float* bq   = (const float*)d_in[5];
    const float* Wk   = (const float*)d_in[6];
    const float* bk   = (const float*)d_in[7];
    const float* Wo   = (const float*)d_in[8];
    const float* bo   = (const float*)d_in[9];

    float* out = (float*)d_out;

    float* pattd;
    cudaGetSymbolAddress((void**)&pattd, g_att_dummy);

    __nv_bfloat16 *xhi, *xlo, *qhi, *qlo, *khi, *klo, *vhi, *vlo, *chi, *clo;
    cudaGetSymbolAddress((void**)&xhi, g_xhi);
    cudaGetSymbolAddress((void**)&xlo, g_xlo);
    cudaGetSymbolAddress((void**)&qhi, g_qhi);
    cudaGetSymbolAddress((void**)&qlo, g_qlo);
    cudaGetSymbolAddress((void**)&khi, g_khi);
    cudaGetSymbolAddress((void**)&klo, g_klo);
    cudaGetSymbolAddress((void**)&vhi, g_vhi);
    cudaGetSymbolAddress((void**)&vlo, g_vlo);
    cudaGetSymbolAddress((void**)&chi, g_chi);
    cudaGetSymbolAddress((void**)&clo, g_clo);

    __nv_bfloat16 *wvhi, *wvlo, *wqhi, *wqlo, *wkhi, *wklo, *wohi, *wolo;
    cudaGetSymbolAddress((void**)&wvhi, g_wvhi);
    cudaGetSymbolAddress((void**)&wvlo, g_wvlo);
    cudaGetSymbolAddress((void**)&wqhi, g_wqhi);
    cudaGetSymbolAddress((void**)&wqlo, g_wqlo);
    cudaGetSymbolAddress((void**)&wkhi, g_wkhi);
    cudaGetSymbolAddress((void**)&wklo, g_wklo);
    cudaGetSymbolAddress((void**)&wohi, g_wohi);
    cudaGetSymbolAddress((void**)&wolo, g_wolo);

    float* patt = ((long)out_size >= TOT_ELEMS) ? (out + OUT_ELEMS) : pattd;

    cudaFuncSetAttribute(attention_mma,
                         cudaFuncAttributeMaxDynamicSharedMemorySize, ATT_SMEM);
    cudaFuncSetAttribute(mma_gemm,
                         cudaFuncAttributeMaxDynamicSharedMemorySize, GEMM_SMEM);

    {
        long n4 = (long)MROWS * GK / 4;
        split_x_kernel<<<(unsigned)((n4 + 255) / 256), 256>>>(
            (const float4*)x, (uint2*)xhi, (uint2*)xlo, n4);
    }
    prep_weight<<<(GK*HID  + 255)/256, 256>>>(Wv, wvhi, wvlo, GK, HID);
    prep_weight<<<(GK*KD   + 255)/256, 256>>>(Wq, wqhi, wqlo, GK, KD);
    prep_weight<<<(GK*KD   + 255)/256, 256>>>(Wk, wkhi, wklo, GK, KD);
    prep_weight<<<(HID*DOUT+ 255)/256, 256>>>(Wo, wohi, wolo, HID, DOUT);

    const int mTiles = MROWS / 128;
    mma_gemm<<<dim3(HID/128, mTiles), 256, GEMM_SMEM>>>(
        xhi, xlo, wvhi, wvlo, bv, nullptr, vhi, vlo, HID, 1);
    mma_gemm<<<dim3(KD/128,  mTiles), 256, GEMM_SMEM>>>(
        xhi, xlo, wqhi, wqlo, bq, nullptr, qhi, qlo, KD, 1);
    mma_gemm<<<dim3(KD/128,  mTiles), 256, GEMM_SMEM>>>(
        xhi, xlo, wkhi, wklo, bk, nullptr, khi, klo, KD, 1);

    attention_mma<<<BATCH, 256, ATT_SMEM>>>(qhi, qlo, khi, klo, vhi, vlo,
                                            mask, patt, chi, clo);

    mma_gemm<<<dim3(DOUT/128, mTiles), 256, GEMM_SMEM>>>(
        chi, clo, wohi, wolo, bo, out, nullptr, nullptr, DOUT, 0);
}

// round 7
// speedup vs baseline: 1.2411x; 1.1884x over previous
#include <cuda_runtime.h>
#include <cuda_bf16.h>
#include <cstdint>

// ---------------- problem constants ----------------
#define BATCH 1024
#define NN    128
#define DIN   256
#define HID   256
#define DOUT  256
#define KD    512
#define MROWS (BATCH*NN)
#define GK    256
#define NCAT  1280    // HID + KD + KD

#define OUT_ELEMS ((long)MROWS*DOUT)
#define ATT_ELEMS ((long)BATCH*NN*NN)
#define TOT_ELEMS (OUT_ELEMS + ATT_ELEMS)

// ---------------- scratch ----------------
__device__ __align__(16) float g_att_dummy[ATT_ELEMS];

__device__ __align__(16) __nv_bfloat16 g_xhi[(long)MROWS*GK];
__device__ __align__(16) __nv_bfloat16 g_xlo[(long)MROWS*GK];
__device__ __align__(16) __nv_bfloat16 g_qhi[(long)MROWS*KD];
__device__ __align__(16) __nv_bfloat16 g_qlo[(long)MROWS*KD];
__device__ __align__(16) __nv_bfloat16 g_khi[(long)MROWS*KD];
__device__ __align__(16) __nv_bfloat16 g_klo[(long)MROWS*KD];
__device__ __align__(16) __nv_bfloat16 g_vhi[(long)MROWS*HID];
__device__ __align__(16) __nv_bfloat16 g_vlo[(long)MROWS*HID];
__device__ __align__(16) __nv_bfloat16 g_chi[(long)MROWS*HID];
__device__ __align__(16) __nv_bfloat16 g_clo[(long)MROWS*HID];

__device__ __align__(16) __nv_bfloat16 g_wcat_hi[NCAT*GK], g_wcat_lo[NCAT*GK];
__device__ __align__(16) __nv_bfloat16 g_wohi[HID*DOUT],  g_wolo[HID*DOUT];
__device__ __align__(16) float g_bcat[NCAT];

// ---------------- helpers ----------------
__device__ __forceinline__ uint32_t smem_u32(const void* p) {
    uint32_t a;
    asm("{ .reg .u64 t; cvta.to.shared.u64 t, %1; cvt.u32.u64 %0, t; }" : "=r"(a) : "l"(p));
    return a;
}
__device__ __forceinline__ void split_bf16(float a, __nv_bfloat16& h, __nv_bfloat16& l) {
    h = __float2bfloat16_rn(a);
    l = __float2bfloat16_rn(a - __bfloat162float(h));
}

#define LDSM4(r0, r1, r2, r3, addr) \
    asm volatile("ldmatrix.sync.aligned.m8n8.x4.shared.b16 {%0,%1,%2,%3}, [%4];" \
                 : "=r"(r0), "=r"(r1), "=r"(r2), "=r"(r3) : "r"(addr))

#define LDSM4T(r0, r1, r2, r3, addr) \
    asm volatile("ldmatrix.sync.aligned.m8n8.x4.trans.shared.b16 {%0,%1,%2,%3}, [%4];" \
                 : "=r"(r0), "=r"(r1), "=r"(r2), "=r"(r3) : "r"(addr))

#define MMA16816(d, a0, a1, a2, a3, b0, b1) \
    asm volatile("mma.sync.aligned.m16n8k16.row.col.f32.bf16.bf16.f32 " \
                 "{%0,%1,%2,%3},{%4,%5,%6,%7},{%8,%9},{%0,%1,%2,%3};" \
                 : "+f"((d)[0]), "+f"((d)[1]), "+f"((d)[2]), "+f"((d)[3]) \
                 : "r"(a0), "r"(a1), "r"(a2), "r"(a3), "r"(b0), "r"(b1))

// ---------------- prep kernels ----------------
__global__ void split_x_kernel(const float4* __restrict__ x,
                               uint2* __restrict__ hi, uint2* __restrict__ lo, long n4) {
    long i = (long)blockIdx.x * blockDim.x + threadIdx.x;
    if (i >= n4) return;
    float4 a = x[i];
    __nv_bfloat16 h0, l0, h1, l1, h2, l2, h3, l3;
    split_bf16(a.x, h0, l0); split_bf16(a.y, h1, l1);
    split_bf16(a.z, h2, l2); split_bf16(a.w, h3, l3);
    __nv_bfloat162 hA = __halves2bfloat162(h0, h1), hB = __halves2bfloat162(h2, h3);
    __nv_bfloat162 lA = __halves2bfloat162(l0, l1), lB = __halves2bfloat162(l2, l3);
    hi[i] = make_uint2(*(uint32_t*)&hA, *(uint32_t*)&hB);
    lo[i] = make_uint2(*(uint32_t*)&lA, *(uint32_t*)&lB);
}

__global__ void prep_weight(const float* __restrict__ W, __nv_bfloat16* __restrict__ hi,
                            __nv_bfloat16* __restrict__ lo, int K, int N) {
    int idx = blockIdx.x * 256 + threadIdx.x;
    if (idx >= K * N) return;
    int k = idx / N, n = idx % N;
    __nv_bfloat16 h, l;
    split_bf16(W[idx], h, l);
    hi[(long)n * K + k] = h;
    lo[(long)n * K + k] = l;
}

__global__ void concat_bias(const float* __restrict__ bv, const float* __restrict__ bq,
                            const float* __restrict__ bk, float* __restrict__ o) {
    int i = blockIdx.x * 256 + threadIdx.x;
    if (i >= NCAT) return;
    o[i] = (i < 256) ? bv[i] : (i < 768 ? bq[i - 256] : bk[i - 768]);
}

// =====================================================================
// bf16x3 mma GEMM (R4-proven mainloop, occ 2).
// mode 0: fp32 C (out GEMM).  mode 2: routed bf16 hi/lo qkv outputs.
// =====================================================================
#define ROWB 144
#define TILE_B (128 * ROWB)
#define GEMM_SMEM (4 * TILE_B)      // 73728

__global__ void __launch_bounds__(256, 2) mma_gemm(
    const __nv_bfloat16* __restrict__ Ahi, const __nv_bfloat16* __restrict__ Alo,
    const __nv_bfloat16* __restrict__ Bhi, const __nv_bfloat16* __restrict__ Blo,
    const float* __restrict__ bias, float* __restrict__ C,
    __nv_bfloat16* __restrict__ Vhi, __nv_bfloat16* __restrict__ Vlo,
    __nv_bfloat16* __restrict__ Qhi, __nv_bfloat16* __restrict__ Qlo,
    __nv_bfloat16* __restrict__ Khi, __nv_bfloat16* __restrict__ Klo,
    int Ncols, int mode)
{
    extern __shared__ char smc[];
    const uint32_t s0  = smem_u32(smc);
    const uint32_t sAh = s0;
    const uint32_t sAl = s0 + TILE_B;
    const uint32_t sBh = s0 + 2 * TILE_B;
    const uint32_t sBl = s0 + 3 * TILE_B;

    const int tid  = threadIdx.x;
    const int wid  = tid >> 5;
    const int lane = tid & 31;
    const int wm   = wid >> 1;
    const int wn   = wid & 1;

    const long mBase = (long)blockIdx.y * 128;
    const int  nBase = blockIdx.x * 128;

    const __nv_bfloat16* Ah = Ahi + mBase * GK;
    const __nv_bfloat16* Al = Alo + mBase * GK;
    const __nv_bfloat16* Bh = Bhi + (long)nBase * GK;
    const __nv_bfloat16* Bl = Blo + (long)nBase * GK;

    float acc[2][8][4];
    #pragma unroll
    for (int a = 0; a < 2; a++)
        #pragma unroll
        for (int b = 0; b < 8; b++)
            #pragma unroll
            for (int c = 0; c < 4; c++) acc[a][b][c] = 0.f;

    const int lrow = tid >> 3;
    const int lq   = tid & 7;
    const uint32_t aOff = (uint32_t)(wm * 32 + (lane & 15)) * ROWB + (lane >> 4) * 16;
    const uint32_t bOff = (uint32_t)(wn * 64 + (lane & 15)) * ROWB + (lane >> 4) * 16;

    for (int kt = 0; kt < 4; kt++) {
        __syncthreads();
        #pragma unroll
        for (int it = 0; it < 4; it++) {
            int r = lrow + it * 32;
            long gsrc = (long)r * GK + kt * 64 + lq * 8;
            uint32_t sdst = (uint32_t)r * ROWB + lq * 16;
            *(uint4*)(smc + 0 * TILE_B + sdst) = *(const uint4*)(Ah + gsrc);
            *(uint4*)(smc + 1 * TILE_B + sdst) = *(const uint4*)(Al + gsrc);
            *(uint4*)(smc + 2 * TILE_B + sdst) = *(const uint4*)(Bh + gsrc);
            *(uint4*)(smc + 3 * TILE_B + sdst) = *(const uint4*)(Bl + gsrc);
        }
        __syncthreads();

        #pragma unroll
        for (int ks = 0; ks < 4; ks++) {
            const uint32_t kByte = ks * 32;
            uint32_t Bf[16], Af[8], Af2[8];
            #pragma unroll
            for (int c = 0; c < 4; c++) {
                uint32_t ad = sBh + bOff + (uint32_t)c * (16 * ROWB) + kByte;
                LDSM4(Bf[c*4+0], Bf[c*4+1], Bf[c*4+2], Bf[c*4+3], ad);
            }
            #pragma unroll
            for (int mt = 0; mt < 2; mt++) {
                uint32_t ad = sAh + aOff + (uint32_t)mt * (16 * ROWB) + kByte;
                LDSM4(Af[mt*4+0], Af[mt*4+1], Af[mt*4+2], Af[mt*4+3], ad);
            }
            #pragma unroll
            for (int mt = 0; mt < 2; mt++) {
                uint32_t ad = sAl + aOff + (uint32_t)mt * (16 * ROWB) + kByte;
                LDSM4(Af2[mt*4+0], Af2[mt*4+1], Af2[mt*4+2], Af2[mt*4+3], ad);
            }
            #pragma unroll
            for (int mt = 0; mt < 2; mt++)
                #pragma unroll
                for (int c = 0; c < 4; c++) {
                    MMA16816(acc[mt][c*2+0], Af[mt*4+0], Af[mt*4+1], Af[mt*4+2], Af[mt*4+3],
                             Bf[c*4+0], Bf[c*4+2]);
                    MMA16816(acc[mt][c*2+1], Af[mt*4+0], Af[mt*4+1], Af[mt*4+2], Af[mt*4+3],
                             Bf[c*4+1], Bf[c*4+3]);
                    MMA16816(acc[mt][c*2+0], Af2[mt*4+0], Af2[mt*4+1], Af2[mt*4+2], Af2[mt*4+3],
                             Bf[c*4+0], Bf[c*4+2]);
                    MMA16816(acc[mt][c*2+1], Af2[mt*4+0], Af2[mt*4+1], Af2[mt*4+2], Af2[mt*4+3],
                             Bf[c*4+1], Bf[c*4+3]);
                }
            #pragma unroll
            for (int c = 0; c < 4; c++) {
                uint32_t ad = sBl + bOff + (uint32_t)c * (16 * ROWB) + kByte;
                LDSM4(Bf[c*4+0], Bf[c*4+1], Bf[c*4+2], Bf[c*4+3], ad);
            }
            #pragma unroll
            for (int mt = 0; mt < 2; mt++)
                #pragma unroll
                for (int c = 0; c < 4; c++) {
                    MMA16816(acc[mt][c*2+0], Af[mt*4+0], Af[mt*4+1], Af[mt*4+2], Af[mt*4+3],
                             Bf[c*4+0], Bf[c*4+2]);
                    MMA16816(acc[mt][c*2+1], Af[mt*4+0], Af[mt*4+1], Af[mt*4+2], Af[mt*4+3],
                             Bf[c*4+1], Bf[c*4+3]);
                }
        }
    }

    const int group = lane >> 2;
    const int tig   = lane & 3;

    if (mode == 0) {
        #pragma unroll
        for (int mt = 0; mt < 2; mt++) {
            long r0 = mBase + wm * 32 + mt * 16 + group;
            long r1 = r0 + 8;
            #pragma unroll
            for (int nt = 0; nt < 8; nt++) {
                int col = nBase + wn * 64 + (nt >> 1) * 16 + (nt & 1) * 8 + tig * 2;
                float b0 = bias[col], b1 = bias[col + 1];
                *(float2*)(C + r0 * Ncols + col) =
                    make_float2(fmaxf(acc[mt][nt][0] + b0, 0.f), fmaxf(acc[mt][nt][1] + b1, 0.f));
                *(float2*)(C + r1 * Ncols + col) =
                    make_float2(fmaxf(acc[mt][nt][2] + b0, 0.f), fmaxf(acc[mt][nt][3] + b1, 0.f));
            }
        }
    } else {
        // qkv routing: nBase in [0,256)->v, [256,768)->q, [768,1280)->k
        __nv_bfloat16 *Dh, *Dl; int cb; int stride;
        if (nBase < 256)      { Dh = Vhi; Dl = Vlo; cb = 0;   stride = HID; }
        else if (nBase < 768) { Dh = Qhi; Dl = Qlo; cb = 256; stride = KD; }
        else                  { Dh = Khi; Dl = Klo; cb = 768; stride = KD; }
        #pragma unroll
        for (int mt = 0; mt < 2; mt++) {
            long r0 = mBase + wm * 32 + mt * 16 + group;
            long r1 = r0 + 8;
            #pragma unroll
            for (int nt = 0; nt < 8; nt++) {
                int ng = nBase + wn * 64 + (nt >> 1) * 16 + (nt & 1) * 8 + tig * 2;
                float b0 = bias[ng], b1 = bias[ng + 1];
                int dcol = ng - cb;
                float v00 = fmaxf(acc[mt][nt][0] + b0, 0.f);
                float v01 = fmaxf(acc[mt][nt][1] + b1, 0.f);
                float v10 = fmaxf(acc[mt][nt][2] + b0, 0.f);
                float v11 = fmaxf(acc[mt][nt][3] + b1, 0.f);
                __nv_bfloat16 h00, l00, h01, l01, h10, l10, h11, l11;
                split_bf16(v00, h00, l00); split_bf16(v01, h01, l01);
                split_bf16(v10, h10, l10); split_bf16(v11, h11, l11);
                *(__nv_bfloat162*)(Dh + r0 * stride + dcol) = __halves2bfloat162(h00, h01);
                *(__nv_bfloat162*)(Dl + r0 * stride + dcol) = __halves2bfloat162(l00, l01);
                *(__nv_bfloat162*)(Dh + r1 * stride + dcol) = __halves2bfloat162(h10, h11);
                *(__nv_bfloat162*)(Dl + r1 * stride + dcol) = __halves2bfloat162(l10, l11);
            }
        }
    }
}

// =====================================================================
// Fused attention: HMMA scores (reg-resident) -> register softmax ->
// HMMA ctx with ldmatrix.trans v (no transpose pass).
// smem (bytes):
//   [0,34816)        Phi  [128][272]
//   [34816,69632)    Plo
//   [69632,143360)   phase1 q/k bufs 4 x 18432
//   [69632,106496)   v tile hi/lo [128][144] x2   (phase3, reuse)
//   [143360,144384)  maxbuf [128][2] f32
//   [144384,145408)  sumbuf [128][2] f32
// =====================================================================
#define ROWP 272
#define P_HI 0
#define P_LO 34816
#define OFF_QK 69632
#define OFF_V  69632
#define ROWV 144
#define V_TILE (128 * ROWV)
#define OFF_RED 143360
#define OFF_SUM 144384
#define ATT_SMEM 145408

__global__ void __launch_bounds__(256, 1) attention_mma(
    const __nv_bfloat16* __restrict__ qhi, const __nv_bfloat16* __restrict__ qlo,
    const __nv_bfloat16* __restrict__ khi, const __nv_bfloat16* __restrict__ klo,
    const __nv_bfloat16* __restrict__ vhi, const __nv_bfloat16* __restrict__ vlo,
    const float* __restrict__ mask, float* __restrict__ att,
    __nv_bfloat16* __restrict__ ctxhi, __nv_bfloat16* __restrict__ ctxlo)
{
    extern __shared__ char sm[];
    const uint32_t s0 = smem_u32(sm);

    const int b    = blockIdx.x;
    const int tid  = threadIdx.x;
    const int wid  = tid >> 5;
    const int lane = tid & 31;
    const int wm   = wid >> 1;
    const int wn   = wid & 1;
    const int lrow = tid >> 3;
    const int lq   = tid & 7;
    const int group = lane >> 2;
    const int tig   = lane & 3;

    float acc[2][8][4];
    #pragma unroll
    for (int a = 0; a < 2; a++)
        #pragma unroll
        for (int bb = 0; bb < 8; bb++)
            #pragma unroll
            for (int c = 0; c < 4; c++) acc[a][bb][c] = 0.f;

    // ---------------- phase 1: S = q @ k^T (acc stays in regs) ----------------
    {
        const __nv_bfloat16* qh = qhi + (long)b * NN * KD;
        const __nv_bfloat16* ql = qlo + (long)b * NN * KD;
        const __nv_bfloat16* kh = khi + (long)b * NN * KD;
        const __nv_bfloat16* kl = klo + (long)b * NN * KD;

        const uint32_t sQh = s0 + OFF_QK;
        const uint32_t sQl = sQh + TILE_B;
        const uint32_t sKh = sQh + 2 * TILE_B;
        const uint32_t sKl = sQh + 3 * TILE_B;

        const uint32_t aOff = (uint32_t)(wm * 32 + (lane & 15)) * ROWB + (lane >> 4) * 16;
        const uint32_t bOff = (uint32_t)(wn * 64 + (lane & 15)) * ROWB + (lane >> 4) * 16;

        for (int kt = 0; kt < 8; kt++) {
            __syncthreads();
            #pragma unroll
            for (int it = 0; it < 4; it++) {
                int r = lrow + it * 32;
                long gsrc = (long)r * KD + kt * 64 + lq * 8;
                uint32_t sdst = (uint32_t)r * ROWB + lq * 16;
                *(uint4*)(sm + OFF_QK + 0 * TILE_B + sdst) = *(const uint4*)(qh + gsrc);
                *(uint4*)(sm + OFF_QK + 1 * TILE_B + sdst) = *(const uint4*)(ql + gsrc);
                *(uint4*)(sm + OFF_QK + 2 * TILE_B + sdst) = *(const uint4*)(kh + gsrc);
                *(uint4*)(sm + OFF_QK + 3 * TILE_B + sdst) = *(const uint4*)(kl + gsrc);
            }
            __syncthreads();

            #pragma unroll
            for (int ks = 0; ks < 4; ks++) {
                const uint32_t kByte = ks * 32;
                uint32_t Bf[16], Af[8], Af2[8];
                #pragma unroll
                for (int c = 0; c < 4; c++) {
                    uint32_t ad = sKh + bOff + (uint32_t)c * (16 * ROWB) + kByte;
                    LDSM4(Bf[c*4+0], Bf[c*4+1], Bf[c*4+2], Bf[c*4+3], ad);
                }
                #pragma unroll
                for (int mt = 0; mt < 2; mt++) {
                    uint32_t ad = sQh + aOff + (uint32_t)mt * (16 * ROWB) + kByte;
                    LDSM4(Af[mt*4+0], Af[mt*4+1], Af[mt*4+2], Af[mt*4+3], ad);
                }
                #pragma unroll
                for (int mt = 0; mt < 2; mt++) {
                    uint32_t ad = sQl + aOff + (uint32_t)mt * (16 * ROWB) + kByte;
                    LDSM4(Af2[mt*4+0], Af2[mt*4+1], Af2[mt*4+2], Af2[mt*4+3], ad);
                }
                #pragma unroll
                for (int mt = 0; mt < 2; mt++)
                    #pragma unroll
                    for (int c = 0; c < 4; c++) {
                        MMA16816(acc[mt][c*2+0], Af[mt*4+0], Af[mt*4+1], Af[mt*4+2], Af[mt*4+3],
                                 Bf[c*4+0], Bf[c*4+2]);
                        MMA16816(acc[mt][c*2+1], Af[mt*4+0], Af[mt*4+1], Af[mt*4+2], Af[mt*4+3],
                                 Bf[c*4+1], Bf[c*4+3]);
                        MMA16816(acc[mt][c*2+0], Af2[mt*4+0], Af2[mt*4+1], Af2[mt*4+2], Af2[mt*4+3],
                                 Bf[c*4+0], Bf[c*4+2]);
                        MMA16816(acc[mt][c*2+1], Af2[mt*4+0], Af2[mt*4+1], Af2[mt*4+2], Af2[mt*4+3],
                                 Bf[c*4+1], Bf[c*4+3]);
                    }
                #pragma unroll
                for (int c = 0; c < 4; c++) {
                    uint32_t ad = sKl + bOff + (uint32_t)c * (16 * ROWB) + kByte;
                    LDSM4(Bf[c*4+0], Bf[c*4+1], Bf[c*4+2], Bf[c*4+3], ad);
                }
                #pragma unroll
                for (int mt = 0; mt < 2; mt++)
                    #pragma unroll
                    for (int c = 0; c < 4; c++) {
                        MMA16816(acc[mt][c*2+0], Af[mt*4+0], Af[mt*4+1], Af[mt*4+2], Af[mt*4+3],
                                 Bf[c*4+0], Bf[c*4+2]);
                        MMA16816(acc[mt][c*2+1], Af[mt*4+0], Af[mt*4+1], Af[mt*4+2], Af[mt*4+3],
                                 Bf[c*4+1], Bf[c*4+3]);
                    }
            }
        }
    }

    // ---------------- phase 2: register softmax ----------------
    {
        const float* mb = mask + (long)b * NN * NN;
        float* attb = att + (long)b * NN * NN;
        float* maxbuf = (float*)(sm + OFF_RED);
        float* sumbuf = (float*)(sm + OFF_SUM);

        // mask + local row max + cross-lane (tig) reduce + publish
        #pragma unroll
        for (int mt = 0; mt < 2; mt++)
            #pragma unroll
            for (int rs = 0; rs < 2; rs++) {
                int row = wm * 32 + mt * 16 + group + rs * 8;
                float mx = -1e30f;
                #pragma unroll
                for (int nt = 0; nt < 8; nt++) {
                    int col = wn * 64 + (nt >> 1) * 16 + (nt & 1) * 8 + tig * 2;
                    float2 m2 = *(const float2*)(mb + (long)row * NN + col);
                    float v0 = acc[mt][nt][rs*2+0] * m2.x - 1000.f * (1.f - m2.x);
                    float v1 = acc[mt][nt][rs*2+1] * m2.y - 1000.f * (1.f - m2.y);
                    acc[mt][nt][rs*2+0] = v0;
                    acc[mt][nt][rs*2+1] = v1;
                    mx = fmaxf(mx, fmaxf(v0, v1));
                }
                mx = fmaxf(mx, __shfl_xor_sync(0xffffffffu, mx, 1));
                mx = fmaxf(mx, __shfl_xor_sync(0xffffffffu, mx, 2));
                if (tig == 0) maxbuf[row * 2 + wn] = mx;
            }
        __syncthreads();

        // exp + local sum + publish
        #pragma unroll
        for (int mt = 0; mt < 2; mt++)
            #pragma unroll
            for (int rs = 0; rs < 2; rs++) {
                int row = wm * 32 + mt * 16 + group + rs * 8;
                float mx = fmaxf(maxbuf[row * 2], maxbuf[row * 2 + 1]);
                float s = 0.f;
                #pragma unroll
                for (int nt = 0; nt < 8; nt++) {
                    float e0 = __expf(acc[mt][nt][rs*2+0] - mx);
                    float e1 = __expf(acc[mt][nt][rs*2+1] - mx);
                    acc[mt][nt][rs*2+0] = e0;
                    acc[mt][nt][rs*2+1] = e1;
                    s += e0 + e1;
                }
                s += __shfl_xor_sync(0xffffffffu, s, 1);
                s += __shfl_xor_sync(0xffffffffu, s, 2);
                if (tig == 0) sumbuf[row * 2 + wn] = s;
            }
        __syncthreads();

        // normalize, write att gmem + P hi/lo smem
        #pragma unroll
        for (int mt = 0; mt < 2; mt++)
            #pragma unroll
            for (int rs = 0; rs < 2; rs++) {
                int row = wm * 32 + mt * 16 + group + rs * 8;
                float inv = 1.f / (sumbuf[row * 2] + sumbuf[row * 2 + 1]);
                #pragma unroll
                for (int nt = 0; nt < 8; nt++) {
                    int col = wn * 64 + (nt >> 1) * 16 + (nt & 1) * 8 + tig * 2;
                    float p0 = acc[mt][nt][rs*2+0] * inv;
                    float p1 = acc[mt][nt][rs*2+1] * inv;
                    *(float2*)(attb + (long)row * NN + col) = make_float2(p0, p1);
                    __nv_bfloat16 h0, l0, h1, l1;
                    split_bf16(p0, h0, l0); split_bf16(p1, h1, l1);
                    *(__nv_bfloat162*)(sm + P_HI + row * ROWP + col * 2) = __halves2bfloat162(h0, h1);
                    *(__nv_bfloat162*)(sm + P_LO + row * ROWP + col * 2) = __halves2bfloat162(l0, l1);
                }
            }
    }

    // ---------------- phase 3: ctx = P @ v (ldmatrix.trans on v) ----------------
    {
        const __nv_bfloat16* vhb = vhi + (long)b * NN * HID;
        const __nv_bfloat16* vlb = vlo + (long)b * NN * HID;
        __nv_bfloat16* chb = ctxhi + (long)b * NN * HID;
        __nv_bfloat16* clb = ctxlo + (long)b * NN * HID;

        const uint32_t sPh = s0 + P_HI;
        const uint32_t sPl = s0 + P_LO;
        const uint32_t sVh = s0 + OFF_V;
        const uint32_t sVl = sVh + V_TILE;

        const uint32_t aOffP = (uint32_t)(wm * 32 + (lane & 15)) * ROWP + (lane >> 4) * 16;
        // trans B lane map: lanes 0-7: k0-7,n0-7 | 8-15: k8-15,n0-7 | 16-23: k0-7,n8-15 | 24-31: k8-15,n8-15
        const uint32_t bOffV = (uint32_t)((lane & 7) + ((lane >> 3) & 1) * 8) * ROWV
                             + (uint32_t)(wn * 32 + (lane >> 4) * 8) * 2;

        const int vnode = tid >> 1;
        const int vch   = (tid & 1) * 4;

        for (int hc = 0; hc < 4; hc++) {
            __syncthreads();
            // vectorized copy of v slice [128 nodes][64 hid] hi+lo
            #pragma unroll
            for (int j = 0; j < 4; j++) {
                int q4 = vch + j;
                long gsrc = (long)vnode * HID + hc * 64 + q4 * 8;
                *(uint4*)(sm + OFF_V + vnode * ROWV + q4 * 16) = *(const uint4*)(vhb + gsrc);
                *(uint4*)(sm + OFF_V + V_TILE + vnode * ROWV + q4 * 16) = *(const uint4*)(vlb + gsrc);
            }
            __syncthreads();

            float acc2[2][4][4];
            #pragma unroll
            for (int a = 0; a < 2; a++)
                #pragma unroll
                for (int bb = 0; bb < 4; bb++)
                    #pragma unroll
                    for (int c = 0; c < 4; c++) acc2[a][bb][c] = 0.f;

            #pragma unroll
            for (int ks = 0; ks < 8; ks++) {
                const uint32_t kByte = ks * 32;          // P: 16 nodes * 2B
                const uint32_t vkOff = (uint32_t)ks * (16 * ROWV);
                uint32_t Bf[8], Af[8], Af2[8];
                #pragma unroll
                for (int c = 0; c < 2; c++) {
                    uint32_t ad = sVh + bOffV + vkOff + (uint32_t)c * 32;
                    LDSM4T(Bf[c*4+0], Bf[c*4+1], Bf[c*4+2], Bf[c*4+3], ad);
                }
                #pragma unroll
                for (int mt = 0; mt < 2; mt++) {
                    uint32_t ad = sPh + aOffP + (uint32_t)mt * (16 * ROWP) + kByte;
                    LDSM4(Af[mt*4+0], Af[mt*4+1], Af[mt*4+2], Af[mt*4+3], ad);
                }
                #pragma unroll
                for (int mt = 0; mt < 2; mt++) {
                    uint32_t ad = sPl + aOffP + (uint32_t)mt * (16 * ROWP) + kByte;
                    LDSM4(Af2[mt*4+0], Af2[mt*4+1], Af2[mt*4+2], Af2[mt*4+3], ad);
                }
                #pragma unroll
                for (int mt = 0; mt < 2; mt++)
                    #pragma unroll
                    for (int c = 0; c < 2; c++) {
                        MMA16816(acc2[mt][c*2+0], Af[mt*4+0], Af[mt*4+1], Af[mt*4+2], Af[mt*4+3],
                                 Bf[c*4+0], Bf[c*4+1]);
                        MMA16816(acc2[mt][c*2+1], Af[mt*4+0], Af[mt*4+1], Af[mt*4+2], Af[mt*4+3],
                                 Bf[c*4+2], Bf[c*4+3]);
                        MMA16816(acc2[mt][c*2+0], Af2[mt*4+0], Af2[mt*4+1], Af2[mt*4+2], Af2[mt*4+3],
                                 Bf[c*4+0], Bf[c*4+1]);
                        MMA16816(acc2[mt][c*2+1], Af2[mt*4+0], Af2[mt*4+1], Af2[mt*4+2], Af2[mt*4+3],
                                 Bf[c*4+2], Bf[c*4+3]);
                    }
                #pragma unroll
                for (int c = 0; c < 2; c++) {
                    uint32_t ad = sVl + bOffV + vkOff + (uint32_t)c * 32;
                    LDSM4T(Bf[c*4+0], Bf[c*4+1], Bf[c*4+2], Bf[c*4+3], ad);
                }
                #pragma unroll
                for (int mt = 0; mt < 2; mt++)
                    #pragma unroll
                    for (int c = 0; c < 2; c++) {
                        MMA16816(acc2[mt][c*2+0], Af[mt*4+0], Af[mt*4+1], Af[mt*4+2], Af[mt*4+3],
                                 Bf[c*4+0], Bf[c*4+1]);
                        MMA16816(acc2[mt][c*2+1], Af[mt*4+0], Af[mt*4+1], Af[mt*4+2], Af[mt*4+3],
                                 Bf[c*4+2], Bf[c*4+3]);
                    }
            }

            #pragma unroll
            for (int mt = 0; mt < 2; mt++) {
                int r0 = wm * 32 + mt * 16 + group;
                int r1 = r0 + 8;
                #pragma unroll
                for (int nt = 0; nt < 4; nt++) {
                    int col = hc * 64 + wn * 32 + (nt >> 1) * 16 + (nt & 1) * 8 + tig * 2;
                    __nv_bfloat16 h00, l00, h01, l01, h10, l10, h11, l11;
                    split_bf16(acc2[mt][nt][0], h00, l00);
                    split_bf16(acc2[mt][nt][1], h01, l01);
                    split_bf16(acc2[mt][nt][2], h10, l10);
                    split_bf16(acc2[mt][nt][3], h11, l11);
                    *(__nv_bfloat162*)(chb + (long)r0 * HID + col) = __halves2bfloat162(h00, h01);
                    *(__nv_bfloat162*)(clb + (long)r0 * HID + col) = __halves2bfloat162(l00, l01);
                    *(__nv_bfloat162*)(chb + (long)r1 * HID + col) = __halves2bfloat162(h10, h11);
                    *(__nv_bfloat162*)(clb + (long)r1 * HID + col) = __halves2bfloat162(l10, l11);
                }
            }
        }
    }
}

// =====================================================================
extern "C" void kernel_launch(void* const* d_in, const int* in_sizes, int n_in,
                              void* d_out, int out_size)
{
    const float* x    = (const float*)d_in[0];
    const float* mask = (const float*)d_in[1];
    const float* Wv   = (const float*)d_in[2];
    const float* bv   = (const float*)d_in[3];
    const float* Wq   = (const float*)d_in[4];
    const float* bq   = (const float*)d_in[5];
    const float* Wk   = (const float*)d_in[6];
    const float* bk   = (const float*)d_in[7];
    const float* Wo   = (const float*)d_in[8];
    const float* bo   = (const float*)d_in[9];

    float* out = (float*)d_out;

    float* pattd;
    cudaGetSymbolAddress((void**)&pattd, g_att_dummy);

    __nv_bfloat16 *xhi, *xlo, *qhi, *qlo, *khi, *klo, *vhi, *vlo, *chi, *clo;
    cudaGetSymbolAddress((void**)&xhi, g_xhi);
    cudaGetSymbolAddress((void**)&xlo, g_xlo);
    cudaGetSymbolAddress((void**)&qhi, g_qhi);
    cudaGetSymbolAddress((void**)&qlo, g_qlo);
    cudaGetSymbolAddress((void**)&khi, g_khi);
    cudaGetSymbolAddress((void**)&klo, g_klo);
    cudaGetSymbolAddress((void**)&vhi, g_vhi);
    cudaGetSymbolAddress((void**)&vlo, g_vlo);
    cudaGetSymbolAddress((void**)&chi, g_chi);
    cudaGetSymbolAddress((void**)&clo, g_clo);

    __nv_bfloat16 *wch, *wcl, *wohi, *wolo;
    float* bcat;
    cudaGetSymbolAddress((void**)&wch,  g_wcat_hi);
    cudaGetSymbolAddress((void**)&wcl,  g_wcat_lo);
    cudaGetSymbolAddress((void**)&wohi, g_wohi);
    cudaGetSymbolAddress((void**)&wolo, g_wolo);
    cudaGetSymbolAddress((void**)&bcat, g_bcat);

    float* patt = ((long)out_size >= TOT_ELEMS) ? (out + OUT_ELEMS) : pattd;

    cudaFuncSetAttribute(attention_mma,
                         cudaFuncAttributeMaxDynamicSharedMemorySize, ATT_SMEM);
    cudaFuncSetAttribute(mma_gemm,
                         cudaFuncAttributeMaxDynamicSharedMemorySize, GEMM_SMEM);

    {
        long n4 = (long)MROWS * GK / 4;
        split_x_kernel<<<(unsigned)((n4 + 255) / 256), 256>>>(
            (const float4*)x, (uint2*)xhi, (uint2*)xlo, n4);
    }
    // weights into concatenated [1280,256] (v rows 0-255, q 256-767, k 768-1279)
    prep_weight<<<(GK*HID  + 255)/256, 256>>>(Wv, wch,              wcl,              GK, HID);
    prep_weight<<<(GK*KD   + 255)/256, 256>>>(Wq, wch + 256L*GK,    wcl + 256L*GK,    GK, KD);
    prep_weight<<<(GK*KD   + 255)/256, 256>>>(Wk, wch + 768L*GK,    wcl + 768L*GK,    GK, KD);
    prep_weight<<<(HID*DOUT+ 255)/256, 256>>>(Wo, wohi, wolo, HID, DOUT);
    concat_bias<<<(NCAT + 255)/256, 256>>>(bv, bq, bk, bcat);

    const int mTiles = MROWS / 128;   // 1024
    // merged qkv GEMM: grid (10, 1024)
    mma_gemm<<<dim3(NCAT/128, mTiles), 256, GEMM_SMEM>>>(
        xhi, xlo, wch, wcl, bcat, nullptr,
        vhi, vlo, qhi, qlo, khi, klo, 0, 2);

    attention_mma<<<BATCH, 256, ATT_SMEM>>>(qhi, qlo, khi, klo, vhi, vlo,
                                            mask, patt, chi, clo);

    // out GEMM
    mma_gemm<<<dim3(DOUT/128, mTiles), 256, GEMM_SMEM>>>(
        chi, clo, wohi, wolo, bo, out,
        nullptr, nullptr, nullptr, nullptr, nullptr, nullptr, DOUT, 0);
}